// round 17
// baseline (speedup 1.0000x reference)
#include <cuda_runtime.h>

#define BATCH  32
#define NPROB  256
#define NT     256          // 8 warps, 1 column per thread
#define NWARP  8
#define INF_F  1e9f
#define ARR_CAP 1024
#define QCAP   (NPROB + ARR_CAP + 8)

// order-preserving float<->uint encoding (a<b <=> enc(a)<enc(b))
__device__ __forceinline__ unsigned ford(float f) {
    unsigned u = __float_as_uint(f);
    return (u & 0x80000000u) ? ~u : (u | 0x80000000u);
}
__device__ __forceinline__ float forddec(unsigned e) {
    unsigned b = (e & 0x80000000u) ? (e ^ 0x80000000u) : ~e;
    return __uint_as_float(b);
}
__device__ __forceinline__ float dist4(float4 P, float4 G) {
    float d0 = P.x - G.x, d1 = P.y - G.y, d2 = P.z - G.z, d3 = P.w - G.w;
    return sqrtf(d0 * d0 + d1 * d1 + d2 * d2 + d3 * d3);
}

__global__ void __launch_bounds__(NT, 1)
hungarian_jv(const float* __restrict__ pred,
             const float* __restrict__ gt,
             float* __restrict__ out,
             int write_totals)
{
    const int b    = blockIdx.x;
    const int t    = threadIdx.x;        // owns col c = t+1 (1-based)
    const int w    = t >> 5;
    const int lane = t & 31;
    const int c    = t + 1;

    __shared__ float4 pred_sh[NPROB];
    __shared__ float  u_sh[NPROB + 1];
    __shared__ int    p_sh[NPROB + 1];      // p[j]=row matched to col j (1-based), 0=free
    __shared__ int    way_sh[NPROB + 1];
    __shared__ float  up_sh[NPROB + 1];     // u[p[j]], phase-static
    __shared__ float4 pp_sh[NPROB + 1];     // pred[p[j]-1], phase-static
    __shared__ __align__(16) unsigned long long keyv[2][NWARP];  // SAP keys (dbl-buffered)
    __shared__ __align__(16) ulonglong2 arrk[NWARP];             // ARR {K1,K2} per warp
    __shared__ int    rowowner[NPROB];
    __shared__ int    freeq[QCAP];
    __shared__ int    head_sh, tail_sh;
    __shared__ float  wsum[NWARP];

    // ---- stage ----
    pred_sh[t] = ((const float4*)pred)[(size_t)b * NPROB + t];
    const float4 g = ((const float4*)gt)[(size_t)b * NPROB + t];
    u_sh[t] = 0.0f; p_sh[t] = 0; rowowner[t] = 0x7fffffff;
    if (t == 0) { u_sh[NPROB] = 0.0f; p_sh[NPROB] = 0; }
    __syncthreads();

    // ---- column reduction (min over squared dists; sqrtf monotone) ----
    float msq = INF_F; int mrow = 0;
    for (int r = 0; r < NPROB; r++) {
        const float4 P = pred_sh[r];
        float d0 = P.x - g.x, d1 = P.y - g.y, d2 = P.z - g.z, d3 = P.w - g.w;
        float sq = d0 * d0 + d1 * d1 + d2 * d2 + d3 * d3;
        if (sq < msq) { msq = sq; mrow = r; }
    }
    float v = sqrtf(msq);
    atomicMin(&rowowner[mrow], t);
    __syncthreads();
    if (rowowner[mrow] == t) p_sh[c] = mrow + 1;   // this column wins its min row
    __syncthreads();
    if (t == 0) {
        int n = 0;
        for (int r = 0; r < NPROB; r++)
            if (rowowner[r] == 0x7fffffff) freeq[n++] = r + 1;   // 1-based rows
        head_sh = 0; tail_sh = n;
    }
    __syncthreads();

    // ---- augmenting row reduction (JV ARR) ----
    int steps = 0;
    while (true) {
        const int head = head_sh, tail = tail_sh;
        if (head >= tail || steps >= ARR_CAP) break;
        steps++;
        const int i = freeq[head];
        const float4 P = pred_sh[i - 1];
        const float rc = dist4(P, g) - v;

        const unsigned e1  = ford(rc);
        const unsigned m1  = __reduce_min_sync(0xffffffffu, e1);
        const unsigned cd1 = (e1 == m1) ? (unsigned)c : 0xffffffffu;
        const unsigned j1w = __reduce_min_sync(0xffffffffu, cd1);
        const bool iown    = (e1 == m1) && ((unsigned)c == j1w);
        const unsigned e2  = iown ? ford(INF_F) : e1;     // min2 excludes j1's column
        const unsigned m2  = __reduce_min_sync(0xffffffffu, e2);
        const unsigned cd2 = (e2 == m2) ? (unsigned)c : 0xffffffffu;
        const unsigned j2w = __reduce_min_sync(0xffffffffu, cd2);
        if (lane == 0)
            arrk[w] = make_ulonglong2((((unsigned long long)m1) << 32) | j1w,
                                      (((unsigned long long)m2) << 32) | j2w);
        __syncthreads();

        unsigned long long K1[NWARP], K2[NWARP];
        #pragma unroll
        for (int q = 0; q < NWARP; q++) { K1[q] = arrk[q].x; K2[q] = arrk[q].y; }
        unsigned long long gm1 = K1[0]; int wd = 0;
        #pragma unroll
        for (int q = 1; q < NWARP; q++) if (K1[q] < gm1) { gm1 = K1[q]; wd = q; }
        unsigned long long gm2 = 0xffffffffffffffffULL;
        #pragma unroll
        for (int q = 0; q < NWARP; q++) {
            unsigned long long cq = (q == wd) ? K2[q] : K1[q];
            if (cq < gm2) gm2 = cq;
        }
        const int   j1 = (int)(gm1 & 0xffffffffu);
        const float u1 = forddec((unsigned)(gm1 >> 32));
        const int   j2 = (int)(gm2 & 0xffffffffu);
        const float u2 = forddec((unsigned)(gm2 >> 32));

        const bool strict = (u1 < u2);
        if (strict && j1 == c) v -= (u2 - u1);
        if (t == 0) {
            int jA = j1;
            if (!strict && p_sh[j1] != 0) jA = j2;
            const int i0 = p_sh[jA];
            p_sh[jA] = i;
            u_sh[i]  = u2;
            int nh = head + 1, nt2 = tail;
            if (i0 != 0) {
                if (strict) { nh = head; freeq[head] = i0; }
                else        { freeq[nt2++] = i0; }
            }
            head_sh = nh; tail_sh = nt2;
        }
        __syncthreads();
    }

    const int h0  = head_sh;
    const int t0q = tail_sh;

    // ---- SAP phases (R12 exchange; 1 col/thread, way in registers) ----
    for (int idx = h0; idx < t0q; idx++) {
        const int i = freeq[idx];

        // phase-static gather: pj in reg; up/pp broadcast arrays in smem
        const int pj = p_sh[c];
        up_sh[c] = u_sh[pj];  pp_sh[c] = pred_sh[pj ? pj - 1 : 0];
        if (t == 0) { p_sh[0] = i; up_sh[0] = u_sh[i]; pp_sh[0] = pred_sh[i - 1]; }
        const unsigned fb = (pj == 0) ? 1u : 0u;

        float minv = INF_F, Smark = 0.0f, S = 0.0f;
        int   wayr = 0;
        bool  used = false;
        int par = 0;
        int j0 = 0, jfreecol;
        __syncthreads();

        while (true) {
            if (j0 == c) { used = true; Smark = S; minv = INF_F; }

            const float4 P  = pp_sh[j0];          // smem broadcast
            const float  uu = up_sh[j0];
            float cur = dist4(P, g) - uu - v;
            if (used) cur = INF_F;
            if (cur < minv) { minv = cur; wayr = j0; }   // reg only

            const unsigned e  = ford(minv);
            const unsigned m  = __reduce_min_sync(0xffffffffu, e);
            const unsigned cd = (e == m) ? (((unsigned)c << 1) | fb) : 0xffffffffu;
            const unsigned jc = __reduce_min_sync(0xffffffffu, cd);
            if (lane == 0)
                keyv[par][w] = (((unsigned long long)m) << 32) | jc;   // single STS pre-BAR
            __syncthreads();

            const ulonglong2 k0 = *(const ulonglong2*)&keyv[par][0];
            const ulonglong2 k1 = *(const ulonglong2*)&keyv[par][2];
            const ulonglong2 k2 = *(const ulonglong2*)&keyv[par][4];
            const ulonglong2 k3 = *(const ulonglong2*)&keyv[par][6];
            unsigned long long bk = k0.x;
            if (k0.y < bk) bk = k0.y;
            if (k1.x < bk) bk = k1.x;
            if (k1.y < bk) bk = k1.y;
            if (k2.x < bk) bk = k2.x;
            if (k2.y < bk) bk = k2.y;
            if (k3.x < bk) bk = k3.x;
            if (k3.y < bk) bk = k3.y;
            const unsigned lo    = (unsigned)(bk & 0xffffffffu);
            const int      j1    = (int)(lo >> 1);
            const float    delta = forddec((unsigned)(bk >> 32));

            S += delta;
            minv -= delta;
            par ^= 1;
            j0 = j1;
            if (lo & 1u) { jfreecol = j1; break; }   // reached a free column
        }

        // flush back-pointer once, then walk
        way_sh[c] = wayr;
        __syncthreads();
        if (t == 0) {
            int j = jfreecol;
            while (j) { const int jn = way_sh[j]; p_sh[j] = p_sh[jn]; j = jn; }
            u_sh[i] += S;
        }
        if (used) { const float d = S - Smark; u_sh[pj] += d; v -= d; }
        __syncthreads();
    }

    // ---- epilogue: col4row[p[c]-1] = c-1 ; per-batch total ----
    const int r = p_sh[c] - 1;
    out[(size_t)b * NPROB + r] = (float)t;
    if (write_totals) {
        float s = dist4(pred_sh[r], g);
        #pragma unroll
        for (int off = 16; off; off >>= 1)
            s += __shfl_xor_sync(0xffffffffu, s, off);
        if (lane == 0) wsum[w] = s;
        __syncthreads();
        if (t == 0) {
            float acc = 0.0f;
            #pragma unroll
            for (int q = 0; q < NWARP; q++) acc += wsum[q];
            out[(size_t)BATCH * NPROB + b] = acc;
        }
    }
}

extern "C" void kernel_launch(void* const* d_in, const int* in_sizes, int n_in,
                              void* d_out, int out_size)
{
    const float* pred = (const float*)d_in[0];
    const float* gt   = (const float*)d_in[1];
    float* out        = (float*)d_out;
    const int wt      = (out_size >= BATCH * NPROB + BATCH) ? 1 : 0;
    hungarian_jv<<<BATCH, NT>>>(pred, gt, out, wt);
}